// round 1
// baseline (speedup 1.0000x reference)
#include <cuda_runtime.h>
#include <math.h>

// ---------------- scratch (device globals; no allocation) ----------------
__device__ float g_t1[64*16*128*128];   // conv1 out
__device__ float g_t2[64*4*64*64];      // conv2 out
__device__ float g_di[64*4*64*64];      // post-VQ 1x1 out
__device__ float g_t3[64*16*128*128];   // convT1 out
__device__ float g_partA[1024*32];
__device__ float g_partC[1024*8];
__device__ float g_partE[1024];
__device__ float g_partF[1024*32];
__device__ float g_partH[4096];
__device__ float g_bn1[32];  // scale[16], shift[16]
__device__ float g_bn2[8];   // scale[4], shift[4]
__device__ float g_bn3[32];

__device__ __forceinline__ float warp_sum(float v){
#pragma unroll
  for (int o = 16; o > 0; o >>= 1) v += __shfl_down_sync(0xffffffffu, v, o);
  return v;
}

// ---------------- kernel A: conv1 (1->16, k4 s2 p1) + BN1 partials ----------------
__global__ void k_conv1(const float* __restrict__ x, const float* __restrict__ w1,
                        const float* __restrict__ b1){
  __shared__ float s_in[66*68];
  __shared__ float s_w[256];
  __shared__ float s_b[16];
  __shared__ float s_red[8*32];
  const int bz = blockIdx.z;
  const int ox0 = blockIdx.x*32, oy0 = blockIdx.y*32;
  const int tid = threadIdx.y*32 + threadIdx.x;
  s_w[tid] = w1[tid];
  if (tid < 16) s_b[tid] = b1[tid];
  const float* xb = x + (size_t)bz*65536;
  for (int j = tid; j < 66*66; j += 256){
    int r = j/66, c = j - r*66;
    int gr = oy0*2 - 1 + r, gc = ox0*2 - 1 + c;
    float v = 0.f;
    if ((unsigned)gr < 256u && (unsigned)gc < 256u) v = xb[gr*256 + gc];
    s_in[r*68 + c] = v;
  }
  __syncthreads();
  float st[32];
#pragma unroll
  for (int v = 0; v < 32; v++) st[v] = 0.f;
  float* outb = g_t1 + (size_t)bz*16*16384;
#pragma unroll
  for (int k = 0; k < 4; k++){
    int ty = threadIdx.y + k*8;
    int tx = threadIdx.x;
    float p[16];
#pragma unroll
    for (int r = 0; r < 4; r++)
#pragma unroll
      for (int c = 0; c < 4; c++)
        p[r*4+c] = s_in[(2*ty+r)*68 + 2*tx + c];
    int off = (oy0+ty)*128 + ox0+tx;
#pragma unroll
    for (int oc = 0; oc < 16; oc++){
      float acc = s_b[oc];
#pragma unroll
      for (int j = 0; j < 16; j++) acc = fmaf(p[j], s_w[oc*16 + j], acc);
      outb[oc*16384 + off] = acc;
      st[oc] += acc;
      st[16+oc] = fmaf(acc, acc, st[16+oc]);
    }
  }
  int lane = tid & 31, warp = tid >> 5;
#pragma unroll
  for (int v = 0; v < 32; v++){
    float r = warp_sum(st[v]);
    if (lane == 0) s_red[warp*32 + v] = r;
  }
  __syncthreads();
  if (tid < 32){
    float t = 0.f;
#pragma unroll
    for (int w = 0; w < 8; w++) t += s_red[w*32 + tid];
    int blk = (blockIdx.z*4 + blockIdx.y)*4 + blockIdx.x;
    g_partA[blk*32 + tid] = t;
  }
}

// ---------------- BN finalize (deterministic double reduce) ----------------
__global__ void k_bnfin(int which, int nblocks, int nch, double invN,
                        const float* __restrict__ g, const float* __restrict__ be){
  const float* part = (which==0) ? g_partA : (which==1) ? g_partC : g_partF;
  float* bn = (which==0) ? g_bn1 : (which==1) ? g_bn2 : g_bn3;
  int c = threadIdx.x;
  if (c >= nch) return;
  double s = 0.0, q = 0.0;
  int stride = 2*nch;
  for (int i = 0; i < nblocks; i++){
    s += (double)part[i*stride + c];
    q += (double)part[i*stride + nch + c];
  }
  double mean = s*invN;
  double var  = q*invN - mean*mean;
  float scale = (float)((double)g[c] / sqrt(var + 1e-5));
  bn[c] = scale;
  bn[nch + c] = be[c] - (float)mean * scale;
}

// ---------------- kernel C: BN1+ReLU + conv2 (16->4, k4 s2 p1) + BN2 partials ----------------
__global__ void k_conv2(const float* __restrict__ w2, const float* __restrict__ b2){
  extern __shared__ float sm[];
  float* s_in = sm;             // 16*1156
  float* s_w  = sm + 16*1156;   // 1024
  __shared__ float s_b[4];
  __shared__ float s_bn[32];
  __shared__ float s_red[8*8];
  const int bz = blockIdx.z;
  const int ox0 = blockIdx.x*16, oy0 = blockIdx.y*16;
  const int tid = threadIdx.y*16 + threadIdx.x;
  for (int j = tid; j < 1024; j += 256) s_w[j] = w2[j];
  if (tid < 4) s_b[tid] = b2[tid];
  if (tid < 32) s_bn[tid] = g_bn1[tid];
  __syncthreads();
  const float* inb = g_t1 + (size_t)bz*16*16384;
  for (int c = 0; c < 16; c++){
    float sc = s_bn[c], sh = s_bn[16+c];
    for (int j = tid; j < 1156; j += 256){
      int r = j/34, cc = j - r*34;
      int gr = 2*oy0 - 1 + r, gc = 2*ox0 - 1 + cc;
      float v = 0.f;
      if ((unsigned)gr < 128u && (unsigned)gc < 128u)
        v = fmaxf(fmaf(inb[c*16384 + gr*128 + gc], sc, sh), 0.f);
      s_in[c*1156 + j] = v;
    }
  }
  __syncthreads();
  int ty = threadIdx.y, tx = threadIdx.x;
  float acc[4];
#pragma unroll
  for (int o = 0; o < 4; o++) acc[o] = s_b[o];
  for (int c = 0; c < 16; c++){
    const float* sp = s_in + c*1156;
#pragma unroll
    for (int ky = 0; ky < 4; ky++){
#pragma unroll
      for (int kx = 0; kx < 4; kx++){
        float v = sp[(2*ty + ky)*34 + 2*tx + kx];
#pragma unroll
        for (int o = 0; o < 4; o++)
          acc[o] = fmaf(v, s_w[((o*16 + c)*4 + ky)*4 + kx], acc[o]);
      }
    }
  }
  float* outb = g_t2 + bz*16384;
  int off = (oy0+ty)*64 + ox0+tx;
  float st[8];
#pragma unroll
  for (int o = 0; o < 4; o++){
    outb[o*4096 + off] = acc[o];
    st[o] = acc[o];
    st[4+o] = acc[o]*acc[o];
  }
  int lane = tid & 31, warp = tid >> 5;
#pragma unroll
  for (int v = 0; v < 8; v++){
    float r = warp_sum(st[v]);
    if (lane == 0) s_red[warp*8 + v] = r;
  }
  __syncthreads();
  if (tid < 8){
    float t = 0.f;
#pragma unroll
    for (int w = 0; w < 8; w++) t += s_red[w*8 + tid];
    int blk = (blockIdx.z*4 + blockIdx.y)*4 + blockIdx.x;
    g_partC[blk*8 + tid] = t;
  }
}

// ---------------- kernel E: BN2+ReLU + pre1x1 + VQ + loss + post1x1 ----------------
__global__ void k_vq(const float* __restrict__ wpre, const float* __restrict__ bpre,
                     const float* __restrict__ emb,
                     const float* __restrict__ wpost, const float* __restrict__ bpost){
  __shared__ float s_e[128];
  __shared__ float s_ee[64];
  __shared__ float s_red[8];
  int tid = threadIdx.x;
  if (tid < 128) s_e[tid] = emb[tid];
  __syncthreads();
  if (tid < 64) s_ee[tid] = s_e[2*tid]*s_e[2*tid] + s_e[2*tid+1]*s_e[2*tid+1];
  __syncthreads();
  int i = blockIdx.x*256 + tid;
  int b = i >> 12, p = i & 4095;
  const float* tb = g_t2 + b*16384 + p;
  float h0 = fmaxf(fmaf(tb[0],     g_bn2[0], g_bn2[4]), 0.f);
  float h1 = fmaxf(fmaf(tb[4096],  g_bn2[1], g_bn2[5]), 0.f);
  float h2 = fmaxf(fmaf(tb[8192],  g_bn2[2], g_bn2[6]), 0.f);
  float h3 = fmaxf(fmaf(tb[12288], g_bn2[3], g_bn2[7]), 0.f);
  float z0 = bpre[0] + wpre[0]*h0 + wpre[1]*h1 + wpre[2]*h2 + wpre[3]*h3;
  float z1 = bpre[1] + wpre[4]*h0 + wpre[5]*h1 + wpre[6]*h2 + wpre[7]*h3;
  float zz = z0*z0 + z1*z1;
  float best = 3.402823466e38f; int bi = 0;
  for (int k = 0; k < 64; k++){
    float d = zz - 2.f*(z0*s_e[2*k] + z1*s_e[2*k+1]) + s_ee[k];
    if (d < best){ best = d; bi = k; }
  }
  float q0 = s_e[2*bi], q1 = s_e[2*bi+1];
  float l = (q0 - z0)*(q0 - z0) + (q1 - z1)*(q1 - z1);
  float qs0 = z0 + (q0 - z0), qs1 = z1 + (q1 - z1);  // straight-through forward
  float* db = g_di + b*16384 + p;
#pragma unroll
  for (int o = 0; o < 4; o++)
    db[o*4096] = bpost[o] + wpost[2*o]*qs0 + wpost[2*o+1]*qs1;
  int lane = tid & 31, warp = tid >> 5;
  float r = warp_sum(l);
  if (lane == 0) s_red[warp] = r;
  __syncthreads();
  if (tid == 0){
    float t = 0.f;
#pragma unroll
    for (int w = 0; w < 8; w++) t += s_red[w];
    g_partE[blockIdx.x] = t;
  }
}

// ---------------- kernel F: convT1 (in4->out16, k4 s2 p1) + BN3 partials ----------------
__global__ void k_convt1(const float* __restrict__ wd1, const float* __restrict__ bd1){
  __shared__ float s_in[4*324];
  __shared__ float s_w[1024];
  __shared__ float s_b[16];
  __shared__ float s_red[8*32];
  const int bz = blockIdx.z;
  const int ox0 = blockIdx.x*32, oy0 = blockIdx.y*32;
  const int tid = threadIdx.y*32 + threadIdx.x;
  for (int j = tid; j < 1024; j += 256) s_w[j] = wd1[j];
  if (tid < 16) s_b[tid] = bd1[tid];
  const int iyb = oy0/2 - 1, ixb = ox0/2 - 1;
  const float* inb = g_di + bz*16384;
  for (int j = tid; j < 1296; j += 256){
    int c = j/324; int rem = j - c*324; int r = rem/18, cc = rem - r*18;
    int iy = iyb + r, ix = ixb + cc;
    float v = 0.f;
    if ((unsigned)iy < 64u && (unsigned)ix < 64u) v = inb[c*4096 + iy*64 + ix];
    s_in[c*324 + rem] = v;
  }
  __syncthreads();
  float st[32];
#pragma unroll
  for (int v = 0; v < 32; v++) st[v] = 0.f;
  float* outb = g_t3 + (size_t)bz*16*16384;
#pragma unroll
  for (int k = 0; k < 4; k++){
    int y  = oy0 + threadIdx.y + k*8;
    int x2 = ox0 + threadIdx.x;
    int iy0 = (y + 1) >> 1, ix0 = (x2 + 1) >> 1;
    int ly = iy0 - iyb, lx = ix0 - ixb;
    int kyA = y + 3 - 2*iy0, kyB = y + 1 - 2*iy0;   // taps for iy0-1, iy0
    int kxA = x2 + 3 - 2*ix0, kxB = x2 + 1 - 2*ix0;
    float acc[16];
#pragma unroll
    for (int o = 0; o < 16; o++) acc[o] = s_b[o];
#pragma unroll
    for (int c = 0; c < 4; c++){
      const float* sp = s_in + c*324;
      float vAA = sp[(ly-1)*18 + lx-1];
      float vAB = sp[(ly-1)*18 + lx];
      float vBA = sp[ly*18 + lx-1];
      float vBB = sp[ly*18 + lx];
      const float* wc = s_w + c*256;
#pragma unroll
      for (int o = 0; o < 16; o++){
        float a = acc[o];
        a = fmaf(vAA, wc[o*16 + kyA*4 + kxA], a);
        a = fmaf(vAB, wc[o*16 + kyA*4 + kxB], a);
        a = fmaf(vBA, wc[o*16 + kyB*4 + kxA], a);
        a = fmaf(vBB, wc[o*16 + kyB*4 + kxB], a);
        acc[o] = a;
      }
    }
    int off = y*128 + x2;
#pragma unroll
    for (int o = 0; o < 16; o++){
      outb[o*16384 + off] = acc[o];
      st[o] += acc[o];
      st[16+o] = fmaf(acc[o], acc[o], st[16+o]);
    }
  }
  int lane = tid & 31, warp = tid >> 5;
#pragma unroll
  for (int v = 0; v < 32; v++){
    float r = warp_sum(st[v]);
    if (lane == 0) s_red[warp*32 + v] = r;
  }
  __syncthreads();
  if (tid < 32){
    float t = 0.f;
#pragma unroll
    for (int w = 0; w < 8; w++) t += s_red[w*32 + tid];
    int blk = (blockIdx.z*4 + blockIdx.y)*4 + blockIdx.x;
    g_partF[blk*32 + tid] = t;
  }
}

// ---------------- kernel H: BN3+ReLU + convT2 (16->1) + tanh + recon partials ----------------
__global__ void k_convt2(const float* __restrict__ x, const float* __restrict__ wd2,
                         const float* __restrict__ bd2, float* __restrict__ out){
  __shared__ float s_in[16*324];
  __shared__ float s_w[256];
  __shared__ float s_bn[32];
  __shared__ float s_red[8];
  const int bz = blockIdx.z;
  const int ox0 = blockIdx.x*32, oy0 = blockIdx.y*32;
  const int tid = threadIdx.y*32 + threadIdx.x;
  s_w[tid] = wd2[tid];
  if (tid < 32) s_bn[tid] = g_bn3[tid];
  float bd = bd2[0];
  __syncthreads();
  const int iyb = oy0/2 - 1, ixb = ox0/2 - 1;
  const float* inb = g_t3 + (size_t)bz*16*16384;
  for (int c = 0; c < 16; c++){
    float sc = s_bn[c], sh = s_bn[16+c];
    for (int j = tid; j < 324; j += 256){
      int r = j/18, cc = j - r*18;
      int iy = iyb + r, ix = ixb + cc;
      float v = 0.f;
      if ((unsigned)iy < 128u && (unsigned)ix < 128u)
        v = fmaxf(fmaf(inb[c*16384 + iy*128 + ix], sc, sh), 0.f);
      s_in[c*324 + j] = v;
    }
  }
  __syncthreads();
  const float* xb = x + (size_t)bz*65536;
  float* ob = out + (size_t)bz*65536;
  float lsum = 0.f;
#pragma unroll
  for (int k = 0; k < 4; k++){
    int y  = oy0 + threadIdx.y + k*8;
    int x2 = ox0 + threadIdx.x;
    int iy0 = (y + 1) >> 1, ix0 = (x2 + 1) >> 1;
    int ly = iy0 - iyb, lx = ix0 - ixb;
    int kyA = y + 3 - 2*iy0, kyB = y + 1 - 2*iy0;
    int kxA = x2 + 3 - 2*ix0, kxB = x2 + 1 - 2*ix0;
    float acc = bd;
#pragma unroll
    for (int c = 0; c < 16; c++){
      const float* sp = s_in + c*324;
      const float* wc = s_w + c*16;
      acc = fmaf(sp[(ly-1)*18 + lx-1], wc[kyA*4 + kxA], acc);
      acc = fmaf(sp[(ly-1)*18 + lx],   wc[kyA*4 + kxB], acc);
      acc = fmaf(sp[ly*18 + lx-1],     wc[kyB*4 + kxA], acc);
      acc = fmaf(sp[ly*18 + lx],       wc[kyB*4 + kxB], acc);
    }
    float o = tanhf(acc);
    int off = y*256 + x2;
    ob[off] = o;
    float d = xb[off] - o;
    lsum = fmaf(d, d, lsum);
  }
  int lane = tid & 31, warp = tid >> 5;
  float r = warp_sum(lsum);
  if (lane == 0) s_red[warp] = r;
  __syncthreads();
  if (tid == 0){
    float t = 0.f;
#pragma unroll
    for (int w = 0; w < 8; w++) t += s_red[w];
    int blk = (blockIdx.z*8 + blockIdx.y)*8 + blockIdx.x;
    g_partH[blk] = t;
  }
}

// ---------------- kernel I: final loss scalar ----------------
__global__ void k_loss(float* __restrict__ out_loss){
  __shared__ double s_red[8];
  int tid = threadIdx.x;
  double e = 0.0, h = 0.0;
  for (int i = tid; i < 1024; i += 256) e += (double)g_partE[i];
  for (int i = tid; i < 4096; i += 256) h += (double)g_partH[i];
  double t = e*1.2/524288.0 + h/4194304.0;  // (codebook + 0.2*commit) + recon
  int lane = tid & 31, warp = tid >> 5;
#pragma unroll
  for (int o = 16; o > 0; o >>= 1) t += __shfl_down_sync(0xffffffffu, t, o);
  if (lane == 0) s_red[warp] = t;
  __syncthreads();
  if (tid == 0){
    double s = 0.0;
    for (int w = 0; w < 8; w++) s += s_red[w];
    out_loss[0] = (float)s;
  }
}

// ---------------- launch ----------------
extern "C" void kernel_launch(void* const* d_in, const int* in_sizes, int n_in,
                              void* d_out, int out_size){
  const float* x    = (const float*)d_in[0];
  const float* w1   = (const float*)d_in[1];
  const float* b1   = (const float*)d_in[2];
  const float* g1   = (const float*)d_in[3];
  const float* be1  = (const float*)d_in[4];
  const float* w2   = (const float*)d_in[5];
  const float* b2   = (const float*)d_in[6];
  const float* g2   = (const float*)d_in[7];
  const float* be2  = (const float*)d_in[8];
  const float* wpre = (const float*)d_in[9];
  const float* bpre = (const float*)d_in[10];
  const float* emb  = (const float*)d_in[11];
  const float* wpost= (const float*)d_in[12];
  const float* bpost= (const float*)d_in[13];
  const float* wd1  = (const float*)d_in[14];
  const float* bd1  = (const float*)d_in[15];
  const float* g3   = (const float*)d_in[16];
  const float* be3  = (const float*)d_in[17];
  const float* wd2  = (const float*)d_in[18];
  const float* bd2  = (const float*)d_in[19];
  float* out = (float*)d_out;

  int smemC = (16*1156 + 1024) * (int)sizeof(float);   // ~78 KB
  cudaFuncSetAttribute(k_conv2, cudaFuncAttributeMaxDynamicSharedMemorySize, smemC);

  k_conv1 <<<dim3(4,4,64), dim3(32,8)>>>(x, w1, b1);
  k_bnfin <<<1,16>>>(0, 1024, 16, 1.0/1048576.0, g1, be1);
  k_conv2 <<<dim3(4,4,64), dim3(16,16), smemC>>>(w2, b2);
  k_bnfin <<<1,4>>>(1, 1024, 4, 1.0/262144.0, g2, be2);
  k_vq    <<<1024,256>>>(wpre, bpre, emb, wpost, bpost);
  k_convt1<<<dim3(4,4,64), dim3(32,8)>>>(wd1, bd1);
  k_bnfin <<<1,16>>>(2, 1024, 16, 1.0/1048576.0, g3, be3);
  k_convt2<<<dim3(8,8,64), dim3(32,8)>>>(x, wd2, bd2, out);
  k_loss  <<<1,256>>>(out + (out_size - 1));
}

// round 2
// speedup vs baseline: 1.6147x; 1.6147x over previous
#include <cuda_runtime.h>
#include <math.h>

// ---------------- scratch (device globals; no allocation) ----------------
__device__ float g_t1[64*16*128*128];   // conv1 out
__device__ float g_t2[64*4*64*64];      // conv2 out
__device__ float g_di[64*4*64*64];      // post-VQ 1x1 out
__device__ float g_t3[64*16*128*128];   // convT1 out
__device__ float g_partA[1024*32];
__device__ float g_partC[1024*8];
__device__ float g_partE[1024];
__device__ float g_partF[1024*32];
__device__ float g_partH[4096];
__device__ float g_bn1[32];  // scale[16], shift[16]
__device__ float g_bn2[8];   // scale[4], shift[4]
__device__ float g_bn3[32];

__device__ __forceinline__ float warp_sum(float v){
#pragma unroll
  for (int o = 16; o > 0; o >>= 1) v += __shfl_down_sync(0xffffffffu, v, o);
  return v;
}

// ---------------- kernel A: conv1 (1->16, k4 s2 p1) + BN1 partials ----------------
__global__ void k_conv1(const float* __restrict__ x, const float* __restrict__ w1,
                        const float* __restrict__ b1){
  __shared__ float s_in[66*68];
  __shared__ float s_w[256];
  __shared__ float s_b[16];
  __shared__ float s_red[8*32];
  const int bz = blockIdx.z;
  const int ox0 = blockIdx.x*32, oy0 = blockIdx.y*32;
  const int tid = threadIdx.y*32 + threadIdx.x;
  s_w[tid] = w1[tid];
  if (tid < 16) s_b[tid] = b1[tid];
  const float* xb = x + (size_t)bz*65536;
  for (int j = tid; j < 66*66; j += 256){
    int r = j/66, c = j - r*66;
    int gr = oy0*2 - 1 + r, gc = ox0*2 - 1 + c;
    float v = 0.f;
    if ((unsigned)gr < 256u && (unsigned)gc < 256u) v = xb[gr*256 + gc];
    s_in[r*68 + c] = v;
  }
  __syncthreads();
  float st[32];
#pragma unroll
  for (int v = 0; v < 32; v++) st[v] = 0.f;
  float* outb = g_t1 + (size_t)bz*16*16384;
#pragma unroll
  for (int k = 0; k < 4; k++){
    int ty = threadIdx.y + k*8;
    int tx = threadIdx.x;
    float p[16];
#pragma unroll
    for (int r = 0; r < 4; r++)
#pragma unroll
      for (int c = 0; c < 4; c++)
        p[r*4+c] = s_in[(2*ty+r)*68 + 2*tx + c];
    int off = (oy0+ty)*128 + ox0+tx;
#pragma unroll
    for (int oc = 0; oc < 16; oc++){
      float acc = s_b[oc];
#pragma unroll
      for (int j = 0; j < 16; j++) acc = fmaf(p[j], s_w[oc*16 + j], acc);
      outb[oc*16384 + off] = acc;
      st[oc] += acc;
      st[16+oc] = fmaf(acc, acc, st[16+oc]);
    }
  }
  int lane = tid & 31, warp = tid >> 5;
#pragma unroll
  for (int v = 0; v < 32; v++){
    float r = warp_sum(st[v]);
    if (lane == 0) s_red[warp*32 + v] = r;
  }
  __syncthreads();
  if (tid < 32){
    float t = 0.f;
#pragma unroll
    for (int w = 0; w < 8; w++) t += s_red[w*32 + tid];
    int blk = (blockIdx.z*4 + blockIdx.y)*4 + blockIdx.x;
    g_partA[blk*32 + tid] = t;
  }
}

// ---------------- BN finalize (parallel, deterministic double tree) ----------------
// grid = nch blocks, 256 threads. Each block reduces 1024 partial pairs for its channel.
__global__ void k_bnfin(int which, int nch, double invN,
                        const float* __restrict__ g, const float* __restrict__ be){
  const float* part = (which==0) ? g_partA : (which==1) ? g_partC : g_partF;
  float* bn = (which==0) ? g_bn1 : (which==1) ? g_bn2 : g_bn3;
  const int c = blockIdx.x;
  const int tid = threadIdx.x;
  const int stride = 2*nch;
  double s = 0.0, q = 0.0;
#pragma unroll
  for (int i = tid; i < 1024; i += 256){
    s += (double)part[i*stride + c];
    q += (double)part[i*stride + nch + c];
  }
#pragma unroll
  for (int o = 16; o > 0; o >>= 1){
    s += __shfl_down_sync(0xffffffffu, s, o);
    q += __shfl_down_sync(0xffffffffu, q, o);
  }
  __shared__ double ss[8], qq[8];
  int lane = tid & 31, warp = tid >> 5;
  if (lane == 0){ ss[warp] = s; qq[warp] = q; }
  __syncthreads();
  if (tid == 0){
    double S = 0.0, Q = 0.0;
#pragma unroll
    for (int w = 0; w < 8; w++){ S += ss[w]; Q += qq[w]; }
    double mean = S*invN;
    double var  = Q*invN - mean*mean;
    float scale = (float)((double)g[c] / sqrt(var + 1e-5));
    bn[c] = scale;
    bn[nch + c] = be[c] - (float)mean * scale;
  }
}

// ---------------- kernel C: BN1+ReLU + conv2 (16->4, k4 s2 p1) + BN2 partials ----------------
__global__ void k_conv2(const float* __restrict__ w2, const float* __restrict__ b2){
  extern __shared__ float sm[];
  float* s_in = sm;             // 16*1156
  float* s_w  = sm + 16*1156;   // 1024
  __shared__ float s_b[4];
  __shared__ float s_bn[32];
  __shared__ float s_red[8*8];
  const int bz = blockIdx.z;
  const int ox0 = blockIdx.x*16, oy0 = blockIdx.y*16;
  const int tid = threadIdx.y*16 + threadIdx.x;
  for (int j = tid; j < 1024; j += 256) s_w[j] = w2[j];
  if (tid < 4) s_b[tid] = b2[tid];
  if (tid < 32) s_bn[tid] = g_bn1[tid];
  __syncthreads();
  const float* inb = g_t1 + (size_t)bz*16*16384;
  for (int c = 0; c < 16; c++){
    float sc = s_bn[c], sh = s_bn[16+c];
    for (int j = tid; j < 1156; j += 256){
      int r = j/34, cc = j - r*34;
      int gr = 2*oy0 - 1 + r, gc = 2*ox0 - 1 + cc;
      float v = 0.f;
      if ((unsigned)gr < 128u && (unsigned)gc < 128u)
        v = fmaxf(fmaf(inb[c*16384 + gr*128 + gc], sc, sh), 0.f);
      s_in[c*1156 + j] = v;
    }
  }
  __syncthreads();
  int ty = threadIdx.y, tx = threadIdx.x;
  float acc[4];
#pragma unroll
  for (int o = 0; o < 4; o++) acc[o] = s_b[o];
  for (int c = 0; c < 16; c++){
    const float* sp = s_in + c*1156;
#pragma unroll
    for (int ky = 0; ky < 4; ky++){
#pragma unroll
      for (int kx = 0; kx < 4; kx++){
        float v = sp[(2*ty + ky)*34 + 2*tx + kx];
#pragma unroll
        for (int o = 0; o < 4; o++)
          acc[o] = fmaf(v, s_w[((o*16 + c)*4 + ky)*4 + kx], acc[o]);
      }
    }
  }
  float* outb = g_t2 + bz*16384;
  int off = (oy0+ty)*64 + ox0+tx;
  float st[8];
#pragma unroll
  for (int o = 0; o < 4; o++){
    outb[o*4096 + off] = acc[o];
    st[o] = acc[o];
    st[4+o] = acc[o]*acc[o];
  }
  int lane = tid & 31, warp = tid >> 5;
#pragma unroll
  for (int v = 0; v < 8; v++){
    float r = warp_sum(st[v]);
    if (lane == 0) s_red[warp*8 + v] = r;
  }
  __syncthreads();
  if (tid < 8){
    float t = 0.f;
#pragma unroll
    for (int w = 0; w < 8; w++) t += s_red[w*8 + tid];
    int blk = (blockIdx.z*4 + blockIdx.y)*4 + blockIdx.x;
    g_partC[blk*8 + tid] = t;
  }
}

// ---------------- kernel E: BN2+ReLU + pre1x1 + VQ + loss + post1x1 ----------------
__global__ void k_vq(const float* __restrict__ wpre, const float* __restrict__ bpre,
                     const float* __restrict__ emb,
                     const float* __restrict__ wpost, const float* __restrict__ bpost){
  __shared__ float s_e[128];
  __shared__ float s_ee[64];
  __shared__ float s_red[8];
  int tid = threadIdx.x;
  if (tid < 128) s_e[tid] = emb[tid];
  __syncthreads();
  if (tid < 64) s_ee[tid] = s_e[2*tid]*s_e[2*tid] + s_e[2*tid+1]*s_e[2*tid+1];
  __syncthreads();
  int i = blockIdx.x*256 + tid;
  int b = i >> 12, p = i & 4095;
  const float* tb = g_t2 + b*16384 + p;
  float h0 = fmaxf(fmaf(tb[0],     g_bn2[0], g_bn2[4]), 0.f);
  float h1 = fmaxf(fmaf(tb[4096],  g_bn2[1], g_bn2[5]), 0.f);
  float h2 = fmaxf(fmaf(tb[8192],  g_bn2[2], g_bn2[6]), 0.f);
  float h3 = fmaxf(fmaf(tb[12288], g_bn2[3], g_bn2[7]), 0.f);
  float z0 = bpre[0] + wpre[0]*h0 + wpre[1]*h1 + wpre[2]*h2 + wpre[3]*h3;
  float z1 = bpre[1] + wpre[4]*h0 + wpre[5]*h1 + wpre[6]*h2 + wpre[7]*h3;
  float zz = z0*z0 + z1*z1;
  float best = 3.402823466e38f; int bi = 0;
  for (int k = 0; k < 64; k++){
    float d = zz - 2.f*(z0*s_e[2*k] + z1*s_e[2*k+1]) + s_ee[k];
    if (d < best){ best = d; bi = k; }
  }
  float q0 = s_e[2*bi], q1 = s_e[2*bi+1];
  float l = (q0 - z0)*(q0 - z0) + (q1 - z1)*(q1 - z1);
  float qs0 = z0 + (q0 - z0), qs1 = z1 + (q1 - z1);  // straight-through forward
  float* db = g_di + b*16384 + p;
#pragma unroll
  for (int o = 0; o < 4; o++)
    db[o*4096] = bpost[o] + wpost[2*o]*qs0 + wpost[2*o+1]*qs1;
  int lane = tid & 31, warp = tid >> 5;
  float r = warp_sum(l);
  if (lane == 0) s_red[warp] = r;
  __syncthreads();
  if (tid == 0){
    float t = 0.f;
#pragma unroll
    for (int w = 0; w < 8; w++) t += s_red[w];
    g_partE[blockIdx.x] = t;
  }
}

// ---------------- kernel F: convT1 (in4->out16, k4 s2 p1) + BN3 partials ----------------
__global__ void k_convt1(const float* __restrict__ wd1, const float* __restrict__ bd1){
  __shared__ float s_in[4*324];
  __shared__ float s_w[1024];
  __shared__ float s_b[16];
  __shared__ float s_red[8*32];
  const int bz = blockIdx.z;
  const int ox0 = blockIdx.x*32, oy0 = blockIdx.y*32;
  const int tid = threadIdx.y*32 + threadIdx.x;
  for (int j = tid; j < 1024; j += 256) s_w[j] = wd1[j];
  if (tid < 16) s_b[tid] = bd1[tid];
  const int iyb = oy0/2 - 1, ixb = ox0/2 - 1;
  const float* inb = g_di + bz*16384;
  for (int j = tid; j < 1296; j += 256){
    int c = j/324; int rem = j - c*324; int r = rem/18, cc = rem - r*18;
    int iy = iyb + r, ix = ixb + cc;
    float v = 0.f;
    if ((unsigned)iy < 64u && (unsigned)ix < 64u) v = inb[c*4096 + iy*64 + ix];
    s_in[c*324 + rem] = v;
  }
  __syncthreads();
  float st[32];
#pragma unroll
  for (int v = 0; v < 32; v++) st[v] = 0.f;
  float* outb = g_t3 + (size_t)bz*16*16384;
#pragma unroll
  for (int k = 0; k < 4; k++){
    int y  = oy0 + threadIdx.y + k*8;
    int x2 = ox0 + threadIdx.x;
    int iy0 = (y + 1) >> 1, ix0 = (x2 + 1) >> 1;
    int ly = iy0 - iyb, lx = ix0 - ixb;
    int kyA = y + 3 - 2*iy0, kyB = y + 1 - 2*iy0;   // taps for iy0-1, iy0
    int kxA = x2 + 3 - 2*ix0, kxB = x2 + 1 - 2*ix0;
    float acc[16];
#pragma unroll
    for (int o = 0; o < 16; o++) acc[o] = s_b[o];
#pragma unroll
    for (int c = 0; c < 4; c++){
      const float* sp = s_in + c*324;
      float vAA = sp[(ly-1)*18 + lx-1];
      float vAB = sp[(ly-1)*18 + lx];
      float vBA = sp[ly*18 + lx-1];
      float vBB = sp[ly*18 + lx];
      const float* wc = s_w + c*256;
#pragma unroll
      for (int o = 0; o < 16; o++){
        float a = acc[o];
        a = fmaf(vAA, wc[o*16 + kyA*4 + kxA], a);
        a = fmaf(vAB, wc[o*16 + kyA*4 + kxB], a);
        a = fmaf(vBA, wc[o*16 + kyB*4 + kxA], a);
        a = fmaf(vBB, wc[o*16 + kyB*4 + kxB], a);
        acc[o] = a;
      }
    }
    int off = y*128 + x2;
#pragma unroll
    for (int o = 0; o < 16; o++){
      outb[o*16384 + off] = acc[o];
      st[o] += acc[o];
      st[16+o] = fmaf(acc[o], acc[o], st[16+o]);
    }
  }
  int lane = tid & 31, warp = tid >> 5;
#pragma unroll
  for (int v = 0; v < 32; v++){
    float r = warp_sum(st[v]);
    if (lane == 0) s_red[warp*32 + v] = r;
  }
  __syncthreads();
  if (tid < 32){
    float t = 0.f;
#pragma unroll
    for (int w = 0; w < 8; w++) t += s_red[w*32 + tid];
    int blk = (blockIdx.z*4 + blockIdx.y)*4 + blockIdx.x;
    g_partF[blk*32 + tid] = t;
  }
}

// ---------------- kernel H: BN3+ReLU + convT2 (16->1) + tanh + recon partials ----------------
__global__ void k_convt2(const float* __restrict__ x, const float* __restrict__ wd2,
                         const float* __restrict__ bd2, float* __restrict__ out){
  __shared__ float s_in[16*324];
  __shared__ float s_w[256];
  __shared__ float s_bn[32];
  __shared__ float s_red[8];
  const int bz = blockIdx.z;
  const int ox0 = blockIdx.x*32, oy0 = blockIdx.y*32;
  const int tid = threadIdx.y*32 + threadIdx.x;
  s_w[tid] = wd2[tid];
  if (tid < 32) s_bn[tid] = g_bn3[tid];
  float bd = bd2[0];
  __syncthreads();
  const int iyb = oy0/2 - 1, ixb = ox0/2 - 1;
  const float* inb = g_t3 + (size_t)bz*16*16384;
  for (int c = 0; c < 16; c++){
    float sc = s_bn[c], sh = s_bn[16+c];
    for (int j = tid; j < 324; j += 256){
      int r = j/18, cc = j - r*18;
      int iy = iyb + r, ix = ixb + cc;
      float v = 0.f;
      if ((unsigned)iy < 128u && (unsigned)ix < 128u)
        v = fmaxf(fmaf(inb[c*16384 + iy*128 + ix], sc, sh), 0.f);
      s_in[c*324 + j] = v;
    }
  }
  __syncthreads();
  const float* xb = x + (size_t)bz*65536;
  float* ob = out + (size_t)bz*65536;
  float lsum = 0.f;
#pragma unroll
  for (int k = 0; k < 4; k++){
    int y  = oy0 + threadIdx.y + k*8;
    int x2 = ox0 + threadIdx.x;
    int iy0 = (y + 1) >> 1, ix0 = (x2 + 1) >> 1;
    int ly = iy0 - iyb, lx = ix0 - ixb;
    int kyA = y + 3 - 2*iy0, kyB = y + 1 - 2*iy0;
    int kxA = x2 + 3 - 2*ix0, kxB = x2 + 1 - 2*ix0;
    float acc = bd;
#pragma unroll
    for (int c = 0; c < 16; c++){
      const float* sp = s_in + c*324;
      const float* wc = s_w + c*16;
      acc = fmaf(sp[(ly-1)*18 + lx-1], wc[kyA*4 + kxA], acc);
      acc = fmaf(sp[(ly-1)*18 + lx],   wc[kyA*4 + kxB], acc);
      acc = fmaf(sp[ly*18 + lx-1],     wc[kyB*4 + kxA], acc);
      acc = fmaf(sp[ly*18 + lx],       wc[kyB*4 + kxB], acc);
    }
    float o = tanhf(acc);
    int off = y*256 + x2;
    ob[off] = o;
    float d = xb[off] - o;
    lsum = fmaf(d, d, lsum);
  }
  int lane = tid & 31, warp = tid >> 5;
  float r = warp_sum(lsum);
  if (lane == 0) s_red[warp] = r;
  __syncthreads();
  if (tid == 0){
    float t = 0.f;
#pragma unroll
    for (int w = 0; w < 8; w++) t += s_red[w];
    int blk = (blockIdx.z*8 + blockIdx.y)*8 + blockIdx.x;
    g_partH[blk] = t;
  }
}

// ---------------- kernel I: final loss scalar ----------------
__global__ void k_loss(float* __restrict__ out_loss){
  __shared__ double s_red[8];
  int tid = threadIdx.x;
  double e = 0.0, h = 0.0;
  for (int i = tid; i < 1024; i += 256) e += (double)g_partE[i];
  for (int i = tid; i < 4096; i += 256) h += (double)g_partH[i];
  double t = e*1.2/524288.0 + h/4194304.0;  // (codebook + 0.2*commit) + recon
  int lane = tid & 31, warp = tid >> 5;
#pragma unroll
  for (int o = 16; o > 0; o >>= 1) t += __shfl_down_sync(0xffffffffu, t, o);
  if (lane == 0) s_red[warp] = t;
  __syncthreads();
  if (tid == 0){
    double s = 0.0;
    for (int w = 0; w < 8; w++) s += s_red[w];
    out_loss[0] = (float)s;
  }
}

// ---------------- launch ----------------
extern "C" void kernel_launch(void* const* d_in, const int* in_sizes, int n_in,
                              void* d_out, int out_size){
  const float* x    = (const float*)d_in[0];
  const float* w1   = (const float*)d_in[1];
  const float* b1   = (const float*)d_in[2];
  const float* g1   = (const float*)d_in[3];
  const float* be1  = (const float*)d_in[4];
  const float* w2   = (const float*)d_in[5];
  const float* b2   = (const float*)d_in[6];
  const float* g2   = (const float*)d_in[7];
  const float* be2  = (const float*)d_in[8];
  const float* wpre = (const float*)d_in[9];
  const float* bpre = (const float*)d_in[10];
  const float* emb  = (const float*)d_in[11];
  const float* wpost= (const float*)d_in[12];
  const float* bpost= (const float*)d_in[13];
  const float* wd1  = (const float*)d_in[14];
  const float* bd1  = (const float*)d_in[15];
  const float* g3   = (const float*)d_in[16];
  const float* be3  = (const float*)d_in[17];
  const float* wd2  = (const float*)d_in[18];
  const float* bd2  = (const float*)d_in[19];
  float* out = (float*)d_out;

  int smemC = (16*1156 + 1024) * (int)sizeof(float);   // ~78 KB
  cudaFuncSetAttribute(k_conv2, cudaFuncAttributeMaxDynamicSharedMemorySize, smemC);

  k_conv1 <<<dim3(4,4,64), dim3(32,8)>>>(x, w1, b1);
  k_bnfin <<<16,256>>>(0, 16, 1.0/1048576.0, g1, be1);
  k_conv2 <<<dim3(4,4,64), dim3(16,16), smemC>>>(w2, b2);
  k_bnfin <<<4,256>>>(1, 4, 1.0/262144.0, g2, be2);
  k_vq    <<<1024,256>>>(wpre, bpre, emb, wpost, bpost);
  k_convt1<<<dim3(4,4,64), dim3(32,8)>>>(wd1, bd1);
  k_bnfin <<<16,256>>>(2, 16, 1.0/1048576.0, g3, be3);
  k_convt2<<<dim3(8,8,64), dim3(32,8)>>>(x, wd2, bd2, out);
  k_loss  <<<1,256>>>(out + (out_size - 1));
}

// round 3
// speedup vs baseline: 1.8225x; 1.1287x over previous
#include <cuda_runtime.h>
#include <math.h>

// ---------------- scratch (device globals; no allocation) ----------------
__device__ float g_t1[64*16*128*128];   // conv1 out
__device__ float g_t2[64*4*64*64];      // conv2 out
__device__ float g_di[64*4*64*64];      // post-VQ 1x1 out
__device__ float g_t3[64*16*128*128];   // convT1 out
__device__ float g_partA[2048*16];
__device__ float g_partC[1024*8];
__device__ float g_partE[1024];
__device__ float g_partF[2048*16];
__device__ float g_partH[4096];
__device__ float g_bn1[32];  // scale[16], shift[16]
__device__ float g_bn2[8];   // scale[4], shift[4]
__device__ float g_bn3[32];

__device__ __forceinline__ float warp_sum(float v){
#pragma unroll
  for (int o = 16; o > 0; o >>= 1) v += __shfl_down_sync(0xffffffffu, v, o);
  return v;
}

// ---------------- kernel A: conv1 (1->16, k4 s2 p1) + BN1 partials ----------------
// grid (4,4,128): z = batch*2 + ocgroup. Each block does 8 output channels.
__global__ void k_conv1(const float* __restrict__ x, const float* __restrict__ w1,
                        const float* __restrict__ b1){
  __shared__ float s_in[66*68];
  __shared__ float s_w[128];
  __shared__ float s_b[8];
  __shared__ float s_red[8*16];
  const int g  = blockIdx.z & 1;
  const int bz = blockIdx.z >> 1;
  const int ox0 = blockIdx.x*32, oy0 = blockIdx.y*32;
  const int tid = threadIdx.y*32 + threadIdx.x;
  if (tid < 128) s_w[tid] = w1[g*128 + tid];
  if (tid < 8)   s_b[tid] = b1[g*8 + tid];
  const float* xb = x + (size_t)bz*65536;
  for (int j = tid; j < 66*66; j += 256){
    int r = j/66, c = j - r*66;
    int gr = oy0*2 - 1 + r, gc = ox0*2 - 1 + c;
    float v = 0.f;
    if ((unsigned)gr < 256u && (unsigned)gc < 256u) v = xb[gr*256 + gc];
    s_in[r*68 + c] = v;
  }
  __syncthreads();
  float st[16];
#pragma unroll
  for (int v = 0; v < 16; v++) st[v] = 0.f;
  float* outb = g_t1 + (size_t)bz*16*16384 + (size_t)g*8*16384;
#pragma unroll
  for (int k = 0; k < 4; k++){
    int ty = threadIdx.y + k*8;
    int tx = threadIdx.x;
    float p[16];
#pragma unroll
    for (int r = 0; r < 4; r++)
#pragma unroll
      for (int c = 0; c < 4; c++)
        p[r*4+c] = s_in[(2*ty+r)*68 + 2*tx + c];
    int off = (oy0+ty)*128 + ox0+tx;
#pragma unroll
    for (int o = 0; o < 8; o += 2){
      float a0 = s_b[o], a1 = s_b[o+1];
#pragma unroll
      for (int j = 0; j < 16; j++){
        a0 = fmaf(p[j], s_w[o*16 + j], a0);
        a1 = fmaf(p[j], s_w[(o+1)*16 + j], a1);
      }
      outb[o*16384 + off]     = a0;
      outb[(o+1)*16384 + off] = a1;
      st[o]   += a0;  st[8+o]   = fmaf(a0, a0, st[8+o]);
      st[o+1] += a1;  st[8+o+1] = fmaf(a1, a1, st[8+o+1]);
    }
  }
  int lane = tid & 31, warp = tid >> 5;
#pragma unroll
  for (int v = 0; v < 16; v++){
    float r = warp_sum(st[v]);
    if (lane == 0) s_red[warp*16 + v] = r;
  }
  __syncthreads();
  if (tid < 16){
    float t = 0.f;
#pragma unroll
    for (int w = 0; w < 8; w++) t += s_red[w*16 + tid];
    int blk = (blockIdx.z*4 + blockIdx.y)*4 + blockIdx.x;   // 0..2047
    g_partA[blk*16 + tid] = t;
  }
}

// ---------------- BN finalize for split-group partials (BN1 / BN3) ----------------
// grid = 16 blocks (one per channel), 256 threads.
__global__ void k_bnfin16(int which, const float* __restrict__ g, const float* __restrict__ be){
  const float* part = (which == 0) ? g_partA : g_partF;
  float* bn = (which == 0) ? g_bn1 : g_bn3;
  const int c = blockIdx.x;
  const int gi = c >> 3, j = c & 7;
  const int tid = threadIdx.x;
  double s = 0.0, q = 0.0;
  for (int i = tid; i < 1024; i += 256){
    int z = 2*(i >> 4) + gi;            // blockIdx.z values containing this group
    int blk = z*16 + (i & 15);
    s += (double)part[blk*16 + j];
    q += (double)part[blk*16 + 8 + j];
  }
#pragma unroll
  for (int o = 16; o > 0; o >>= 1){
    s += __shfl_down_sync(0xffffffffu, s, o);
    q += __shfl_down_sync(0xffffffffu, q, o);
  }
  __shared__ double ss[8], qq[8];
  int lane = tid & 31, warp = tid >> 5;
  if (lane == 0){ ss[warp] = s; qq[warp] = q; }
  __syncthreads();
  if (tid == 0){
    double S = 0.0, Q = 0.0;
#pragma unroll
    for (int w = 0; w < 8; w++){ S += ss[w]; Q += qq[w]; }
    const double invN = 1.0/1048576.0;
    double mean = S*invN;
    double var  = Q*invN - mean*mean;
    float scale = (float)((double)g[c] / sqrt(var + 1e-5));
    bn[c] = scale;
    bn[16 + c] = be[c] - (float)mean * scale;
  }
}

// ---------------- BN2 finalize (4 channels, partC [1024][8]) ----------------
__global__ void k_bnfin4(const float* __restrict__ g, const float* __restrict__ be){
  const int c = blockIdx.x;
  const int tid = threadIdx.x;
  double s = 0.0, q = 0.0;
  for (int i = tid; i < 1024; i += 256){
    s += (double)g_partC[i*8 + c];
    q += (double)g_partC[i*8 + 4 + c];
  }
#pragma unroll
  for (int o = 16; o > 0; o >>= 1){
    s += __shfl_down_sync(0xffffffffu, s, o);
    q += __shfl_down_sync(0xffffffffu, q, o);
  }
  __shared__ double ss[8], qq[8];
  int lane = tid & 31, warp = tid >> 5;
  if (lane == 0){ ss[warp] = s; qq[warp] = q; }
  __syncthreads();
  if (tid == 0){
    double S = 0.0, Q = 0.0;
#pragma unroll
    for (int w = 0; w < 8; w++){ S += ss[w]; Q += qq[w]; }
    const double invN = 1.0/262144.0;
    double mean = S*invN;
    double var  = Q*invN - mean*mean;
    float scale = (float)((double)g[c] / sqrt(var + 1e-5));
    g_bn2[c] = scale;
    g_bn2[4 + c] = be[c] - (float)mean * scale;
  }
}

// ---------------- kernel C: BN1+ReLU + conv2 (16->4, k4 s2 p1) + BN2 partials ----------------
// Two-phase smem staging: 8 input channels at a time (static smem, ~41 KB).
__global__ void k_conv2(const float* __restrict__ w2, const float* __restrict__ b2){
  __shared__ float s_in[8*1156];
  __shared__ float s_w[1024];
  __shared__ float s_b[4];
  __shared__ float s_bn[32];
  __shared__ float s_red[8*8];
  const int bz = blockIdx.z;
  const int ox0 = blockIdx.x*16, oy0 = blockIdx.y*16;
  const int tid = threadIdx.y*16 + threadIdx.x;
  for (int j = tid; j < 1024; j += 256) s_w[j] = w2[j];
  if (tid < 4) s_b[tid] = b2[tid];
  if (tid < 32) s_bn[tid] = g_bn1[tid];
  __syncthreads();
  const float* inb = g_t1 + (size_t)bz*16*16384;
  const int ty = threadIdx.y, tx = threadIdx.x;
  float acc[4];
#pragma unroll
  for (int o = 0; o < 4; o++) acc[o] = s_b[o];
#pragma unroll
  for (int ph = 0; ph < 2; ph++){
    for (int c8 = 0; c8 < 8; c8++){
      int c = ph*8 + c8;
      float sc = s_bn[c], sh = s_bn[16+c];
      for (int j = tid; j < 1156; j += 256){
        int r = j/34, cc = j - r*34;
        int gr = 2*oy0 - 1 + r, gc = 2*ox0 - 1 + cc;
        float v = 0.f;
        if ((unsigned)gr < 128u && (unsigned)gc < 128u)
          v = fmaxf(fmaf(inb[c*16384 + gr*128 + gc], sc, sh), 0.f);
        s_in[c8*1156 + j] = v;
      }
    }
    __syncthreads();
    for (int c8 = 0; c8 < 8; c8++){
      int c = ph*8 + c8;
      const float* sp = s_in + c8*1156;
#pragma unroll
      for (int ky = 0; ky < 4; ky++){
#pragma unroll
        for (int kx = 0; kx < 4; kx++){
          float v = sp[(2*ty + ky)*34 + 2*tx + kx];
#pragma unroll
          for (int o = 0; o < 4; o++)
            acc[o] = fmaf(v, s_w[((o*16 + c)*4 + ky)*4 + kx], acc[o]);
        }
      }
    }
    __syncthreads();
  }
  float* outb = g_t2 + bz*16384;
  int off = (oy0+ty)*64 + ox0+tx;
  float st[8];
#pragma unroll
  for (int o = 0; o < 4; o++){
    outb[o*4096 + off] = acc[o];
    st[o] = acc[o];
    st[4+o] = acc[o]*acc[o];
  }
  int lane = tid & 31, warp = tid >> 5;
#pragma unroll
  for (int v = 0; v < 8; v++){
    float r = warp_sum(st[v]);
    if (lane == 0) s_red[warp*8 + v] = r;
  }
  __syncthreads();
  if (tid < 8){
    float t = 0.f;
#pragma unroll
    for (int w = 0; w < 8; w++) t += s_red[w*8 + tid];
    int blk = (blockIdx.z*4 + blockIdx.y)*4 + blockIdx.x;
    g_partC[blk*8 + tid] = t;
  }
}

// ---------------- kernel E: BN2+ReLU + pre1x1 + VQ + loss + post1x1 ----------------
__global__ void k_vq(const float* __restrict__ wpre, const float* __restrict__ bpre,
                     const float* __restrict__ emb,
                     const float* __restrict__ wpost, const float* __restrict__ bpost){
  __shared__ float s_e[128];
  __shared__ float s_ee[64];
  __shared__ float s_red[8];
  int tid = threadIdx.x;
  if (tid < 128) s_e[tid] = emb[tid];
  __syncthreads();
  if (tid < 64) s_ee[tid] = s_e[2*tid]*s_e[2*tid] + s_e[2*tid+1]*s_e[2*tid+1];
  __syncthreads();
  int i = blockIdx.x*256 + tid;
  int b = i >> 12, p = i & 4095;
  const float* tb = g_t2 + b*16384 + p;
  float h0 = fmaxf(fmaf(tb[0],     g_bn2[0], g_bn2[4]), 0.f);
  float h1 = fmaxf(fmaf(tb[4096],  g_bn2[1], g_bn2[5]), 0.f);
  float h2 = fmaxf(fmaf(tb[8192],  g_bn2[2], g_bn2[6]), 0.f);
  float h3 = fmaxf(fmaf(tb[12288], g_bn2[3], g_bn2[7]), 0.f);
  float z0 = bpre[0] + wpre[0]*h0 + wpre[1]*h1 + wpre[2]*h2 + wpre[3]*h3;
  float z1 = bpre[1] + wpre[4]*h0 + wpre[5]*h1 + wpre[6]*h2 + wpre[7]*h3;
  float zz = z0*z0 + z1*z1;
  float best = 3.402823466e38f; int bi = 0;
  for (int k = 0; k < 64; k++){
    float d = zz - 2.f*(z0*s_e[2*k] + z1*s_e[2*k+1]) + s_ee[k];
    if (d < best){ best = d; bi = k; }
  }
  float q0 = s_e[2*bi], q1 = s_e[2*bi+1];
  float l = (q0 - z0)*(q0 - z0) + (q1 - z1)*(q1 - z1);
  float qs0 = z0 + (q0 - z0), qs1 = z1 + (q1 - z1);  // straight-through forward
  float* db = g_di + b*16384 + p;
#pragma unroll
  for (int o = 0; o < 4; o++)
    db[o*4096] = bpost[o] + wpost[2*o]*qs0 + wpost[2*o+1]*qs1;
  int lane = tid & 31, warp = tid >> 5;
  float r = warp_sum(l);
  if (lane == 0) s_red[warp] = r;
  __syncthreads();
  if (tid == 0){
    float t = 0.f;
#pragma unroll
    for (int w = 0; w < 8; w++) t += s_red[w];
    g_partE[blockIdx.x] = t;
  }
}

// ---------------- kernel F: convT1 (in4->out16, k4 s2 p1) + BN3 partials ----------------
// grid (4,4,128): z = batch*2 + ocgroup (8 output channels per block).
__global__ void k_convt1(const float* __restrict__ wd1, const float* __restrict__ bd1){
  __shared__ float s_in[4*324];
  __shared__ float s_w[512];
  __shared__ float s_b[8];
  __shared__ float s_red[8*16];
  const int g  = blockIdx.z & 1;
  const int bz = blockIdx.z >> 1;
  const int ox0 = blockIdx.x*32, oy0 = blockIdx.y*32;
  const int tid = threadIdx.y*32 + threadIdx.x;
  // wd1 layout [in=4][out=16][4][4]; load out channels g*8..g*8+7
  for (int j = tid; j < 512; j += 256){
    int c = j >> 7, rem = j & 127;           // rem = o8*16 + tap
    int o8 = rem >> 4, tap = rem & 15;
    s_w[j] = wd1[c*256 + (g*8 + o8)*16 + tap];
  }
  if (tid < 8) s_b[tid] = bd1[g*8 + tid];
  const int iyb = oy0/2 - 1, ixb = ox0/2 - 1;
  const float* inb = g_di + bz*16384;
  for (int j = tid; j < 1296; j += 256){
    int c = j/324; int rem = j - c*324; int r = rem/18, cc = rem - r*18;
    int iy = iyb + r, ix = ixb + cc;
    float v = 0.f;
    if ((unsigned)iy < 64u && (unsigned)ix < 64u) v = inb[c*4096 + iy*64 + ix];
    s_in[c*324 + rem] = v;
  }
  __syncthreads();
  float st[16];
#pragma unroll
  for (int v = 0; v < 16; v++) st[v] = 0.f;
  float* outb = g_t3 + (size_t)bz*16*16384 + (size_t)g*8*16384;
#pragma unroll
  for (int k = 0; k < 4; k++){
    int y  = oy0 + threadIdx.y + k*8;
    int x2 = ox0 + threadIdx.x;
    int iy0 = (y + 1) >> 1, ix0 = (x2 + 1) >> 1;
    int ly = iy0 - iyb, lx = ix0 - ixb;
    int kyA = y + 3 - 2*iy0, kyB = y + 1 - 2*iy0;   // taps for iy0-1, iy0
    int kxA = x2 + 3 - 2*ix0, kxB = x2 + 1 - 2*ix0;
    float acc[8];
#pragma unroll
    for (int o = 0; o < 8; o++) acc[o] = s_b[o];
#pragma unroll
    for (int c = 0; c < 4; c++){
      const float* sp = s_in + c*324;
      float vAA = sp[(ly-1)*18 + lx-1];
      float vAB = sp[(ly-1)*18 + lx];
      float vBA = sp[ly*18 + lx-1];
      float vBB = sp[ly*18 + lx];
      const float* wc = s_w + c*128;
#pragma unroll
      for (int o = 0; o < 8; o++){
        float a = acc[o];
        a = fmaf(vAA, wc[o*16 + kyA*4 + kxA], a);
        a = fmaf(vAB, wc[o*16 + kyA*4 + kxB], a);
        a = fmaf(vBA, wc[o*16 + kyB*4 + kxA], a);
        a = fmaf(vBB, wc[o*16 + kyB*4 + kxB], a);
        acc[o] = a;
      }
    }
    int off = y*128 + x2;
#pragma unroll
    for (int o = 0; o < 8; o++){
      outb[o*16384 + off] = acc[o];
      st[o] += acc[o];
      st[8+o] = fmaf(acc[o], acc[o], st[8+o]);
    }
  }
  int lane = tid & 31, warp = tid >> 5;
#pragma unroll
  for (int v = 0; v < 16; v++){
    float r = warp_sum(st[v]);
    if (lane == 0) s_red[warp*16 + v] = r;
  }
  __syncthreads();
  if (tid < 16){
    float t = 0.f;
#pragma unroll
    for (int w = 0; w < 8; w++) t += s_red[w*16 + tid];
    int blk = (blockIdx.z*4 + blockIdx.y)*4 + blockIdx.x;
    g_partF[blk*16 + tid] = t;
  }
}

// ---------------- kernel H: BN3+ReLU + convT2 (16->1) + tanh + recon partials ----------------
__global__ void k_convt2(const float* __restrict__ x, const float* __restrict__ wd2,
                         const float* __restrict__ bd2, float* __restrict__ out){
  __shared__ float s_in[16*324];
  __shared__ float s_w[256];
  __shared__ float s_bn[32];
  __shared__ float s_red[8];
  const int bz = blockIdx.z;
  const int ox0 = blockIdx.x*32, oy0 = blockIdx.y*32;
  const int tid = threadIdx.y*32 + threadIdx.x;
  s_w[tid] = wd2[tid];
  if (tid < 32) s_bn[tid] = g_bn3[tid];
  float bd = bd2[0];
  __syncthreads();
  const int iyb = oy0/2 - 1, ixb = ox0/2 - 1;
  const float* inb = g_t3 + (size_t)bz*16*16384;
  for (int c = 0; c < 16; c++){
    float sc = s_bn[c], sh = s_bn[16+c];
    for (int j = tid; j < 324; j += 256){
      int r = j/18, cc = j - r*18;
      int iy = iyb + r, ix = ixb + cc;
      float v = 0.f;
      if ((unsigned)iy < 128u && (unsigned)ix < 128u)
        v = fmaxf(fmaf(inb[c*16384 + iy*128 + ix], sc, sh), 0.f);
      s_in[c*324 + j] = v;
    }
  }
  __syncthreads();
  const float* xb = x + (size_t)bz*65536;
  float* ob = out + (size_t)bz*65536;
  float lsum = 0.f;
#pragma unroll
  for (int k = 0; k < 4; k++){
    int y  = oy0 + threadIdx.y + k*8;
    int x2 = ox0 + threadIdx.x;
    int iy0 = (y + 1) >> 1, ix0 = (x2 + 1) >> 1;
    int ly = iy0 - iyb, lx = ix0 - ixb;
    int kyA = y + 3 - 2*iy0, kyB = y + 1 - 2*iy0;
    int kxA = x2 + 3 - 2*ix0, kxB = x2 + 1 - 2*ix0;
    float acc = bd;
#pragma unroll
    for (int c = 0; c < 16; c++){
      const float* sp = s_in + c*324;
      const float* wc = s_w + c*16;
      acc = fmaf(sp[(ly-1)*18 + lx-1], wc[kyA*4 + kxA], acc);
      acc = fmaf(sp[(ly-1)*18 + lx],   wc[kyA*4 + kxB], acc);
      acc = fmaf(sp[ly*18 + lx-1],     wc[kyB*4 + kxA], acc);
      acc = fmaf(sp[ly*18 + lx],       wc[kyB*4 + kxB], acc);
    }
    float o = tanhf(acc);
    int off = y*256 + x2;
    ob[off] = o;
    float d = xb[off] - o;
    lsum = fmaf(d, d, lsum);
  }
  int lane = tid & 31, warp = tid >> 5;
  float r = warp_sum(lsum);
  if (lane == 0) s_red[warp] = r;
  __syncthreads();
  if (tid == 0){
    float t = 0.f;
#pragma unroll
    for (int w = 0; w < 8; w++) t += s_red[w];
    int blk = (blockIdx.z*8 + blockIdx.y)*8 + blockIdx.x;
    g_partH[blk] = t;
  }
}

// ---------------- kernel I: final loss scalar ----------------
__global__ void k_loss(float* __restrict__ out_loss){
  __shared__ double s_red[8];
  int tid = threadIdx.x;
  double e = 0.0, h = 0.0;
  for (int i = tid; i < 1024; i += 256) e += (double)g_partE[i];
  for (int i = tid; i < 4096; i += 256) h += (double)g_partH[i];
  double t = e*1.2/524288.0 + h/4194304.0;  // (codebook + 0.2*commit) + recon
  int lane = tid & 31, warp = tid >> 5;
#pragma unroll
  for (int o = 16; o > 0; o >>= 1) t += __shfl_down_sync(0xffffffffu, t, o);
  if (lane == 0) s_red[warp] = t;
  __syncthreads();
  if (tid == 0){
    double s = 0.0;
    for (int w = 0; w < 8; w++) s += s_red[w];
    out_loss[0] = (float)s;
  }
}

// ---------------- launch ----------------
extern "C" void kernel_launch(void* const* d_in, const int* in_sizes, int n_in,
                              void* d_out, int out_size){
  const float* x    = (const float*)d_in[0];
  const float* w1   = (const float*)d_in[1];
  const float* b1   = (const float*)d_in[2];
  const float* g1   = (const float*)d_in[3];
  const float* be1  = (const float*)d_in[4];
  const float* w2   = (const float*)d_in[5];
  const float* b2   = (const float*)d_in[6];
  const float* g2   = (const float*)d_in[7];
  const float* be2  = (const float*)d_in[8];
  const float* wpre = (const float*)d_in[9];
  const float* bpre = (const float*)d_in[10];
  const float* emb  = (const float*)d_in[11];
  const float* wpost= (const float*)d_in[12];
  const float* bpost= (const float*)d_in[13];
  const float* wd1  = (const float*)d_in[14];
  const float* bd1  = (const float*)d_in[15];
  const float* g3   = (const float*)d_in[16];
  const float* be3  = (const float*)d_in[17];
  const float* wd2  = (const float*)d_in[18];
  const float* bd2  = (const float*)d_in[19];
  float* out = (float*)d_out;

  k_conv1  <<<dim3(4,4,128), dim3(32,8)>>>(x, w1, b1);
  k_bnfin16<<<16,256>>>(0, g1, be1);
  k_conv2  <<<dim3(4,4,64), dim3(16,16)>>>(w2, b2);
  k_bnfin4 <<<4,256>>>(g2, be2);
  k_vq     <<<1024,256>>>(wpre, bpre, emb, wpost, bpost);
  k_convt1 <<<dim3(4,4,128), dim3(32,8)>>>(wd1, bd1);
  k_bnfin16<<<16,256>>>(1, g3, be3);
  k_convt2 <<<dim3(8,8,64), dim3(32,8)>>>(x, wd2, bd2, out);
  k_loss   <<<1,256>>>(out + (out_size - 1));
}